// round 8
// baseline (speedup 1.0000x reference)
#include <cuda_runtime.h>

#define NQ    12
#define DEPTH 4
#define DIM   4096
#define HID   64
#define NPAR  (DEPTH*NQ*3)   // 144
#define TPB   256
#define NG    (DEPTH*NQ)     // 48

__device__ __forceinline__ int swz(int i) { return i ^ ((i >> 4) & 0xF); }

__device__ __forceinline__ float2 fma2(float2 a, float2 b, float2 c) {
    float2 d;
    asm("fma.rn.f32x2 %0, %1, %2, %3;"
        : "=l"(reinterpret_cast<unsigned long long&>(d))
        : "l"(reinterpret_cast<unsigned long long&>(a)),
          "l"(reinterpret_cast<unsigned long long&>(b)),
          "l"(reinterpret_cast<unsigned long long&>(c)));
    return d;
}
__device__ __forceinline__ float2 mul2(float2 a, float2 b) {
    float2 d;
    asm("mul.rn.f32x2 %0, %1, %2;"
        : "=l"(reinterpret_cast<unsigned long long&>(d))
        : "l"(reinterpret_cast<unsigned long long&>(a)),
          "l"(reinterpret_cast<unsigned long long&>(b)));
    return d;
}
__device__ __forceinline__ float2 add2(float2 a, float2 b) {
    float2 d;
    asm("add.rn.f32x2 %0, %1, %2;"
        : "=l"(reinterpret_cast<unsigned long long&>(d))
        : "l"(reinterpret_cast<unsigned long long&>(a)),
          "l"(reinterpret_cast<unsigned long long&>(b)));
    return d;
}
__device__ __forceinline__ float2 swp(float2 v) { return make_float2(v.y, v.x); }

__global__ __launch_bounds__(TPB, 3)
void qgen_kernel(const float* __restrict__ noise,
                 const float* __restrict__ W1, const float* __restrict__ b1,
                 const float* __restrict__ W2, const float* __restrict__ b2,
                 const float* __restrict__ W3, const float* __restrict__ b3,
                 const float* __restrict__ W4, const float* __restrict__ b4,
                 float* __restrict__ out)
{
    __shared__ float2 sv[DIM];          // 32 KB exchange buffer (swizzled)
    __shared__ float  sh_h[HID];
    __shared__ float  sc_s[NPAR], sc_c[NPAR];
    __shared__ float2 gC[NG][6];        // cd, cds0, cds1, co0, co1, cos
    __shared__ float  sh_red[(TPB/32)*NQ];
    __shared__ float  sh_meas[NQ];
    __shared__ float  sh_h2[HID];

    const int row  = blockIdx.x;
    const int tid  = threadIdx.x;
    const int lane = tid & 31;
    const int w    = tid >> 5;

    // ---- front MLP: h = tanh(noise@W1+b1) ----
    if (tid < HID) {
        float acc = b1[tid];
        #pragma unroll
        for (int k = 0; k < NQ; k++)
            acc += noise[row*NQ + k] * W1[k*HID + tid];
        sh_h[tid] = tanhf(acc);
    }
    __syncthreads();
    if (tid < NPAR) {
        float acc = b2[tid];
        #pragma unroll
        for (int j = 0; j < HID; j++)
            acc += sh_h[j] * W2[j*NPAR + tid];
        float s, c;
        __sincosf(0.5f * acc, &s, &c);
        sc_s[tid] = s; sc_c[tid] = c;
    }
    __syncthreads();
    if (tid < NG) {
        float sa = sc_s[tid*3+0], ca = sc_c[tid*3+0];
        float sb = sc_s[tid*3+1], cb = sc_c[tid*3+1];
        float sg = sc_s[tid*3+2], cg = sc_c[tid*3+2];
        float u00r =  cg*cb*ca + sg*sb*sa;
        float u00i =  cg*sb*sa - sg*cb*ca;
        float u01r = -(cg*sb*ca + sg*cb*sa);
        float u01i =  sg*sb*ca - cg*cb*sa;
        gC[tid][0] = make_float2( u00r,  u00r);   // cd
        gC[tid][1] = make_float2(-u00i,  u00i);   // cds0
        gC[tid][2] = make_float2( u00i, -u00i);   // cds1
        gC[tid][3] = make_float2( u01r,  u01r);   // co0
        gC[tid][4] = make_float2(-u01r, -u01r);   // co1
        gC[tid][5] = make_float2(-u01i,  u01i);   // cos
    }

    // ---- phase-1 layout: i = w[11:9] | lane[8:4] | k[3:0] ----
    float2 amp[16];
    #pragma unroll
    for (int k = 0; k < 16; k++) amp[k] = make_float2(0.0f, 0.0f);
    if (tid == 0) amp[0].x = 1.0f;
    __syncthreads();

    #pragma unroll 1
    for (int l = 0; l < DEPTH; l++) {
        const int gb = l * NQ;

        // -- reg gates on local bits 0..3 (qubits 11..8) --
        #pragma unroll
        for (int b = 0; b < 4; b++) {
            const float2 cd   = gC[gb + 11 - b][0];
            const float2 cds0 = gC[gb + 11 - b][1];
            const float2 cds1 = gC[gb + 11 - b][2];
            const float2 co0  = gC[gb + 11 - b][3];
            const float2 co1  = gC[gb + 11 - b][4];
            const float2 cos_ = gC[gb + 11 - b][5];
            #pragma unroll
            for (int m = 0; m < 8; m++) {
                int k0 = ((m >> b) << (b + 1)) | (m & ((1 << b) - 1));
                int k1 = k0 | (1 << b);
                float2 a0 = amp[k0], a1 = amp[k1];
                float2 s0 = swp(a0), s1 = swp(a1);
                // depth-3 trees
                float2 t0a = fma2(cd,  a0, mul2(cds0, s0));
                float2 t0b = fma2(co0, a1, mul2(cos_, s1));
                float2 t1a = fma2(co1, a0, mul2(cos_, s0));
                float2 t1b = fma2(cd,  a1, mul2(cds1, s1));
                amp[k0] = add2(t0a, t0b);
                amp[k1] = add2(t1a, t1b);
            }
        }

        // -- shfl gates on lane bits 4..7 (qubits 7..4), shuffles batched x4 --
        #pragma unroll
        for (int lb = 0; lb < 4; lb++) {
            const int g = gb + 7 - lb;
            const bool side = (lane >> lb) & 1;
            const float2 cd   = gC[g][0];
            const float2 cds  = side ? gC[g][2] : gC[g][1];
            const float2 co   = side ? gC[g][4] : gC[g][3];
            const float2 cos_ = gC[g][5];
            #pragma unroll
            for (int kb = 0; kb < 16; kb += 4) {
                float2 o[4];
                #pragma unroll
                for (int j = 0; j < 4; j++) {
                    o[j].x = __shfl_xor_sync(0xffffffffu, amp[kb+j].x, 1 << lb);
                    o[j].y = __shfl_xor_sync(0xffffffffu, amp[kb+j].y, 1 << lb);
                }
                #pragma unroll
                for (int j = 0; j < 4; j++) {
                    float2 m = amp[kb+j];
                    float2 ta = fma2(cd, m, mul2(cds, swp(m)));
                    float2 tb = fma2(co, o[j], mul2(cos_, swp(o[j])));
                    amp[kb+j] = add2(ta, tb);
                }
            }
        }

        // -- transpose to phase-2: k' = i[11:8], lane' = i[7:3], w' = i[2:0] --
        #pragma unroll
        for (int k = 0; k < 16; k++)
            sv[swz((w << 9) | (lane << 4) | k)] = amp[k];
        __syncthreads();
        #pragma unroll
        for (int k = 0; k < 16; k++)
            amp[k] = sv[swz((k << 8) | (lane << 3) | w)];
        __syncthreads();

        // -- reg gates on global bits 8..11 (qubits 3..0): local bits 0..3 --
        #pragma unroll
        for (int b = 0; b < 4; b++) {
            const float2 cd   = gC[gb + 3 - b][0];
            const float2 cds0 = gC[gb + 3 - b][1];
            const float2 cds1 = gC[gb + 3 - b][2];
            const float2 co0  = gC[gb + 3 - b][3];
            const float2 co1  = gC[gb + 3 - b][4];
            const float2 cos_ = gC[gb + 3 - b][5];
            #pragma unroll
            for (int m = 0; m < 8; m++) {
                int k0 = ((m >> b) << (b + 1)) | (m & ((1 << b) - 1));
                int k1 = k0 | (1 << b);
                float2 a0 = amp[k0], a1 = amp[k1];
                float2 s0 = swp(a0), s1 = swp(a1);
                float2 t0a = fma2(cd,  a0, mul2(cds0, s0));
                float2 t0b = fma2(co0, a1, mul2(cos_, s1));
                float2 t1a = fma2(co1, a0, mul2(cos_, s0));
                float2 t1b = fma2(cd,  a1, mul2(cds1, s1));
                amp[k0] = add2(t0a, t0b);
                amp[k1] = add2(t1a, t1b);
            }
        }

        // -- CNOT-ring permutation scatter, fused with transpose back to L0 --
        #pragma unroll
        for (int k = 0; k < 16; k++) {
            int x  = (k << 8) | (lane << 3) | w;
            int ys = x;
            ys ^= ys >> 1; ys ^= ys >> 2; ys ^= ys >> 4; ys ^= ys >> 8;
            int y = (ys & 0x7FF) | (((ys ^ (x >> 11)) & 1) << 11);
            sv[swz(y)] = amp[k];
        }
        __syncthreads();
        #pragma unroll
        for (int k = 0; k < 16; k++)
            amp[k] = sv[swz((w << 9) | (lane << 4) | k)];
        __syncthreads();
    }

    // ---- measurement from registers (phase-1 layout) ----
    float P = 0.0f;
    float zb[4] = {0.0f, 0.0f, 0.0f, 0.0f};
    #pragma unroll
    for (int k = 0; k < 16; k++) {
        float pk = amp[k].x*amp[k].x + amp[k].y*amp[k].y;
        P += pk;
        #pragma unroll
        for (int b = 0; b < 4; b++)
            zb[b] += ((k >> b) & 1) ? -pk : pk;
    }
    float z[NQ];
    const int hi = (w << 9) | (lane << 4);
    #pragma unroll
    for (int q = 0; q < 8; q++)
        z[q] = ((hi >> (11 - q)) & 1) ? -P : P;
    #pragma unroll
    for (int q = 8; q < 12; q++)
        z[q] = zb[11 - q];

    #pragma unroll
    for (int q = 0; q < NQ; q++) {
        #pragma unroll
        for (int s = 16; s > 0; s >>= 1)
            z[q] += __shfl_xor_sync(0xffffffffu, z[q], s);
    }
    if (lane == 0) {
        #pragma unroll
        for (int q = 0; q < NQ; q++) sh_red[w*NQ + q] = z[q];
    }
    __syncthreads();
    if (tid < NQ) {
        float acc = 0.0f;
        #pragma unroll
        for (int ww = 0; ww < TPB/32; ww++) acc += sh_red[ww*NQ + tid];
        sh_meas[tid] = acc;
    }
    __syncthreads();

    // ---- back MLP ----
    if (tid < HID) {
        float acc = b3[tid];
        #pragma unroll
        for (int k = 0; k < NQ; k++)
            acc += sh_meas[k] * W3[k*HID + tid];
        sh_h2[tid] = tanhf(acc);
    }
    __syncthreads();
    if (tid < 2) {
        float acc = b4[tid];
        #pragma unroll
        for (int j = 0; j < HID; j++)
            acc += sh_h2[j] * W4[j*2 + tid];
        out[row*2 + tid] = acc;
    }
}

extern "C" void kernel_launch(void* const* d_in, const int* in_sizes, int n_in,
                              void* d_out, int out_size)
{
    const float* noise = (const float*)d_in[0];
    const float* W1 = (const float*)d_in[1];
    const float* b1 = (const float*)d_in[2];
    const float* W2 = (const float*)d_in[3];
    const float* b2 = (const float*)d_in[4];
    const float* W3 = (const float*)d_in[5];
    const float* b3 = (const float*)d_in[6];
    const float* W4 = (const float*)d_in[7];
    const float* b4 = (const float*)d_in[8];
    float* out = (float*)d_out;

    int batch = in_sizes[0] / NQ;   // 4096
    qgen_kernel<<<batch, TPB>>>(noise, W1, b1, W2, b2, W3, b3, W4, b4, out);
}

// round 9
// speedup vs baseline: 1.0908x; 1.0908x over previous
#include <cuda_runtime.h>

#define NQ    12
#define DEPTH 4
#define DIM   4096
#define HID   64
#define NPAR  (DEPTH*NQ*3)   // 144
#define TPB   256
#define NG    (DEPTH*NQ)     // 48

__device__ __forceinline__ int swz(int i) { return i ^ ((i >> 4) & 0xF); }

__device__ __forceinline__ float2 fma2(float2 a, float2 b, float2 c) {
    float2 d;
    asm("fma.rn.f32x2 %0, %1, %2, %3;"
        : "=l"(reinterpret_cast<unsigned long long&>(d))
        : "l"(reinterpret_cast<unsigned long long&>(a)),
          "l"(reinterpret_cast<unsigned long long&>(b)),
          "l"(reinterpret_cast<unsigned long long&>(c)));
    return d;
}
__device__ __forceinline__ float2 mul2(float2 a, float2 b) {
    float2 d;
    asm("mul.rn.f32x2 %0, %1, %2;"
        : "=l"(reinterpret_cast<unsigned long long&>(d))
        : "l"(reinterpret_cast<unsigned long long&>(a)),
          "l"(reinterpret_cast<unsigned long long&>(b)));
    return d;
}
__device__ __forceinline__ float2 swp(float2 v) { return make_float2(v.y, v.x); }

// pair update (chain form, 8 packed ops = 16 real FMA, the minimum):
//   amp[k0] = cd*a0 + cds0*s0 + co0*a1 + cos*s1
//   amp[k1] = co1*a0 + cos*s0 + cd*a1 + cds1*s1     (sX = swap(aX))

__global__ __launch_bounds__(TPB, 3)
void qgen_kernel(const float* __restrict__ noise,
                 const float* __restrict__ W1, const float* __restrict__ b1,
                 const float* __restrict__ W2, const float* __restrict__ b2,
                 const float* __restrict__ W3, const float* __restrict__ b3,
                 const float* __restrict__ W4, const float* __restrict__ b4,
                 float* __restrict__ out)
{
    __shared__ float2 sv[DIM];          // 32 KB exchange buffer (swizzled)
    __shared__ float  sh_h[HID];
    __shared__ float  sc_s[NPAR], sc_c[NPAR];
    __shared__ float2 gC[NG][6];        // cd, cds0, cds1, co0, co1, cos
    __shared__ float  sh_red[(TPB/32)*NQ];
    __shared__ float  sh_meas[NQ];
    __shared__ float  sh_h2[HID];

    const int row  = blockIdx.x;
    const int tid  = threadIdx.x;
    const int lane = tid & 31;
    const int w    = tid >> 5;

    // ---- front MLP: h = tanh(noise@W1+b1) ----
    if (tid < HID) {
        float acc = b1[tid];
        #pragma unroll
        for (int k = 0; k < NQ; k++)
            acc += noise[row*NQ + k] * W1[k*HID + tid];
        sh_h[tid] = tanhf(acc);
    }
    __syncthreads();
    if (tid < NPAR) {
        float acc = b2[tid];
        #pragma unroll
        for (int j = 0; j < HID; j++)
            acc += sh_h[j] * W2[j*NPAR + tid];
        float s, c;
        __sincosf(0.5f * acc, &s, &c);
        sc_s[tid] = s; sc_c[tid] = c;
    }
    __syncthreads();
    if (tid < NG) {
        float sa = sc_s[tid*3+0], ca = sc_c[tid*3+0];
        float sb = sc_s[tid*3+1], cb = sc_c[tid*3+1];
        float sg = sc_s[tid*3+2], cg = sc_c[tid*3+2];
        float u00r =  cg*cb*ca + sg*sb*sa;
        float u00i =  cg*sb*sa - sg*cb*ca;
        float u01r = -(cg*sb*ca + sg*cb*sa);
        float u01i =  sg*sb*ca - cg*cb*sa;
        gC[tid][0] = make_float2( u00r,  u00r);   // cd
        gC[tid][1] = make_float2(-u00i,  u00i);   // cds0
        gC[tid][2] = make_float2( u00i, -u00i);   // cds1
        gC[tid][3] = make_float2( u01r,  u01r);   // co0
        gC[tid][4] = make_float2(-u01r, -u01r);   // co1
        gC[tid][5] = make_float2(-u01i,  u01i);   // cos
    }

    // ---- phase-1 layout: i = w[11:9] | lane[8:4] | k[3:0] ----
    float2 amp[16];
    #pragma unroll
    for (int k = 0; k < 16; k++) amp[k] = make_float2(0.0f, 0.0f);
    if (tid == 0) amp[0].x = 1.0f;
    __syncthreads();

    #pragma unroll 1
    for (int l = 0; l < DEPTH; l++) {
        const int gb = l * NQ;

        // -- reg gates on local bits 0..3 (qubits 11..8) --
        #pragma unroll
        for (int b = 0; b < 4; b++) {
            const float2 cd   = gC[gb + 11 - b][0];
            const float2 cds0 = gC[gb + 11 - b][1];
            const float2 cds1 = gC[gb + 11 - b][2];
            const float2 co0  = gC[gb + 11 - b][3];
            const float2 co1  = gC[gb + 11 - b][4];
            const float2 cos_ = gC[gb + 11 - b][5];
            #pragma unroll
            for (int m = 0; m < 8; m++) {
                int k0 = ((m >> b) << (b + 1)) | (m & ((1 << b) - 1));
                int k1 = k0 | (1 << b);
                float2 a0 = amp[k0], a1 = amp[k1];
                float2 s0 = swp(a0), s1 = swp(a1);
                amp[k0] = fma2(cd,  a0, fma2(cds0, s0, fma2(co0, a1, mul2(cos_, s1))));
                amp[k1] = fma2(co1, a0, fma2(cos_, s0, fma2(cd,  a1, mul2(cds1, s1))));
            }
        }

        // -- shfl gates on lane bits 4..7 (qubits 7..4) --
        #pragma unroll
        for (int lb = 0; lb < 4; lb++) {
            const int g = gb + 7 - lb;
            const bool side = (lane >> lb) & 1;
            const float2 cd   = gC[g][0];
            const float2 cds  = side ? gC[g][2] : gC[g][1];
            const float2 co   = side ? gC[g][4] : gC[g][3];
            const float2 cos_ = gC[g][5];
            #pragma unroll
            for (int k = 0; k < 16; k++) {
                float2 o;
                o.x = __shfl_xor_sync(0xffffffffu, amp[k].x, 1 << lb);
                o.y = __shfl_xor_sync(0xffffffffu, amp[k].y, 1 << lb);
                float2 m = amp[k];
                float2 sm = swp(m), so = swp(o);
                amp[k] = fma2(cd, m, fma2(cds, sm, fma2(co, o, mul2(cos_, so))));
            }
        }

        // -- transpose to phase-2: k' = i[11:8], lane' = i[7:3], w' = i[2:0] --
        #pragma unroll
        for (int k = 0; k < 16; k++)
            sv[swz((w << 9) | (lane << 4) | k)] = amp[k];
        __syncthreads();
        #pragma unroll
        for (int k = 0; k < 16; k++)
            amp[k] = sv[swz((k << 8) | (lane << 3) | w)];
        __syncthreads();

        // -- reg gates on global bits 8..11 (qubits 3..0): local bits 0..3 --
        #pragma unroll
        for (int b = 0; b < 4; b++) {
            const float2 cd   = gC[gb + 3 - b][0];
            const float2 cds0 = gC[gb + 3 - b][1];
            const float2 cds1 = gC[gb + 3 - b][2];
            const float2 co0  = gC[gb + 3 - b][3];
            const float2 co1  = gC[gb + 3 - b][4];
            const float2 cos_ = gC[gb + 3 - b][5];
            #pragma unroll
            for (int m = 0; m < 8; m++) {
                int k0 = ((m >> b) << (b + 1)) | (m & ((1 << b) - 1));
                int k1 = k0 | (1 << b);
                float2 a0 = amp[k0], a1 = amp[k1];
                float2 s0 = swp(a0), s1 = swp(a1);
                amp[k0] = fma2(cd,  a0, fma2(cds0, s0, fma2(co0, a1, mul2(cos_, s1))));
                amp[k1] = fma2(co1, a0, fma2(cos_, s0, fma2(cd,  a1, mul2(cds1, s1))));
            }
        }

        // -- CNOT-ring permutation scatter, fused with transpose back to L0 --
        #pragma unroll
        for (int k = 0; k < 16; k++) {
            int x  = (k << 8) | (lane << 3) | w;
            int ys = x;
            ys ^= ys >> 1; ys ^= ys >> 2; ys ^= ys >> 4; ys ^= ys >> 8;
            int y = (ys & 0x7FF) | (((ys ^ (x >> 11)) & 1) << 11);
            sv[swz(y)] = amp[k];
        }
        __syncthreads();
        #pragma unroll
        for (int k = 0; k < 16; k++)
            amp[k] = sv[swz((w << 9) | (lane << 4) | k)];
        __syncthreads();
    }

    // ---- measurement from registers (phase-1 layout) ----
    float P = 0.0f;
    float zb[4] = {0.0f, 0.0f, 0.0f, 0.0f};
    #pragma unroll
    for (int k = 0; k < 16; k++) {
        float pk = amp[k].x*amp[k].x + amp[k].y*amp[k].y;
        P += pk;
        #pragma unroll
        for (int b = 0; b < 4; b++)
            zb[b] += ((k >> b) & 1) ? -pk : pk;
    }
    float z[NQ];
    const int hi = (w << 9) | (lane << 4);
    #pragma unroll
    for (int q = 0; q < 8; q++)
        z[q] = ((hi >> (11 - q)) & 1) ? -P : P;
    #pragma unroll
    for (int q = 8; q < 12; q++)
        z[q] = zb[11 - q];

    #pragma unroll
    for (int q = 0; q < NQ; q++) {
        #pragma unroll
        for (int s = 16; s > 0; s >>= 1)
            z[q] += __shfl_xor_sync(0xffffffffu, z[q], s);
    }
    if (lane == 0) {
        #pragma unroll
        for (int q = 0; q < NQ; q++) sh_red[w*NQ + q] = z[q];
    }
    __syncthreads();
    if (tid < NQ) {
        float acc = 0.0f;
        #pragma unroll
        for (int ww = 0; ww < TPB/32; ww++) acc += sh_red[ww*NQ + tid];
        sh_meas[tid] = acc;
    }
    __syncthreads();

    // ---- back MLP ----
    if (tid < HID) {
        float acc = b3[tid];
        #pragma unroll
        for (int k = 0; k < NQ; k++)
            acc += sh_meas[k] * W3[k*HID + tid];
        sh_h2[tid] = tanhf(acc);
    }
    __syncthreads();
    if (tid < 2) {
        float acc = b4[tid];
        #pragma unroll
        for (int j = 0; j < HID; j++)
            acc += sh_h2[j] * W4[j*2 + tid];
        out[row*2 + tid] = acc;
    }
}

extern "C" void kernel_launch(void* const* d_in, const int* in_sizes, int n_in,
                              void* d_out, int out_size)
{
    const float* noise = (const float*)d_in[0];
    const float* W1 = (const float*)d_in[1];
    const float* b1 = (const float*)d_in[2];
    const float* W2 = (const float*)d_in[3];
    const float* b2 = (const float*)d_in[4];
    const float* W3 = (const float*)d_in[5];
    const float* b3 = (const float*)d_in[6];
    const float* W4 = (const float*)d_in[7];
    const float* b4 = (const float*)d_in[8];
    float* out = (float*)d_out;

    int batch = in_sizes[0] / NQ;   // 4096
    qgen_kernel<<<batch, TPB>>>(noise, W1, b1, W2, b2, W3, b3, W4, b4, out);
}

// round 14
// speedup vs baseline: 1.1360x; 1.0413x over previous
#include <cuda_runtime.h>

#define NQ    12
#define DEPTH 4
#define DIM   4096
#define HID   64
#define NPAR  (DEPTH*NQ*3)   // 144
#define TPB   256
#define NG    (DEPTH*NQ)     // 48

__device__ __forceinline__ int swz(int i) { return i ^ ((i >> 4) & 0xF); }

__device__ __forceinline__ float2 fma2(float2 a, float2 b, float2 c) {
    float2 d;
    asm("fma.rn.f32x2 %0, %1, %2, %3;"
        : "=l"(reinterpret_cast<unsigned long long&>(d))
        : "l"(reinterpret_cast<unsigned long long&>(a)),
          "l"(reinterpret_cast<unsigned long long&>(b)),
          "l"(reinterpret_cast<unsigned long long&>(c)));
    return d;
}
__device__ __forceinline__ float2 mul2(float2 a, float2 b) {
    float2 d;
    asm("mul.rn.f32x2 %0, %1, %2;"
        : "=l"(reinterpret_cast<unsigned long long&>(d))
        : "l"(reinterpret_cast<unsigned long long&>(a)),
          "l"(reinterpret_cast<unsigned long long&>(b)));
    return d;
}
__device__ __forceinline__ float2 swp(float2 v) { return make_float2(v.y, v.x); }

__global__ __launch_bounds__(TPB, 3)
void qgen_kernel(const float* __restrict__ noise,
                 const float* __restrict__ W1, const float* __restrict__ b1,
                 const float* __restrict__ W2, const float* __restrict__ b2,
                 const float* __restrict__ W3, const float* __restrict__ b3,
                 const float* __restrict__ W4, const float* __restrict__ b4,
                 float* __restrict__ out)
{
    extern __shared__ float2 sv[];      // 2 x 32 KB double-buffered exchange
    __shared__ float  sh_h[HID];
    __shared__ float  sc_s[NPAR], sc_c[NPAR];
    __shared__ float2 gC[NG][6];        // cd, cds0, cds1, co0, co1, cos
    __shared__ float  sh_red[(TPB/32)*NQ];
    __shared__ float  sh_meas[NQ];
    __shared__ float  sh_h2[HID];

    const int row  = blockIdx.x;
    const int tid  = threadIdx.x;
    const int lane = tid & 31;
    const int w    = tid >> 5;
    const int l4   = lane >> 4;     // lane bit 4
    const int llo  = lane & 15;     // lane bits 0-3

    // ---- front MLP: h = tanh(noise@W1+b1) ----
    if (tid < HID) {
        float acc = b1[tid];
        #pragma unroll
        for (int k = 0; k < NQ; k++)
            acc += noise[row*NQ + k] * W1[k*HID + tid];
        sh_h[tid] = tanhf(acc);
    }
    __syncthreads();
    if (tid < NPAR) {
        float acc = b2[tid];
        #pragma unroll
        for (int j = 0; j < HID; j++)
            acc += sh_h[j] * W2[j*NPAR + tid];
        float s, c;
        __sincosf(0.5f * acc, &s, &c);
        sc_s[tid] = s; sc_c[tid] = c;
    }
    __syncthreads();
    if (tid < NG) {
        float sa = sc_s[tid*3+0], ca = sc_c[tid*3+0];
        float sb = sc_s[tid*3+1], cb = sc_c[tid*3+1];
        float sg = sc_s[tid*3+2], cg = sc_c[tid*3+2];
        float u00r =  cg*cb*ca + sg*sb*sa;
        float u00i =  cg*sb*sa - sg*cb*ca;
        float u01r = -(cg*sb*ca + sg*cb*sa);
        float u01i =  sg*sb*ca - cg*cb*sa;
        gC[tid][0] = make_float2( u00r,  u00r);   // cd
        gC[tid][1] = make_float2(-u00i,  u00i);   // cds0
        gC[tid][2] = make_float2( u00i, -u00i);   // cds1
        gC[tid][3] = make_float2( u01r,  u01r);   // co0
        gC[tid][4] = make_float2(-u01r, -u01r);   // co1
        gC[tid][5] = make_float2(-u01i,  u01i);   // cos
    }

    // ---- layout A: i = w[11:9] | lane[8:4] | k[3:0] ----
    float2 amp[16];
    #pragma unroll
    for (int k = 0; k < 16; k++) amp[k] = make_float2(0.0f, 0.0f);
    if (tid == 0) amp[0].x = 1.0f;
    __syncthreads();

    // chain-form pair update (8 packed ops = 16 real FMA, minimal)
    #define GATE_REG(GIDX)                                                          \
    {                                                                               \
        const float2 cd   = gC[GIDX][0];                                            \
        const float2 cds0 = gC[GIDX][1];                                            \
        const float2 cds1 = gC[GIDX][2];                                            \
        const float2 co0  = gC[GIDX][3];                                            \
        const float2 co1  = gC[GIDX][4];                                            \
        const float2 cos_ = gC[GIDX][5];                                            \
        _Pragma("unroll")                                                           \
        for (int m = 0; m < 8; m++) {                                               \
            int k0 = ((m >> b) << (b + 1)) | (m & ((1 << b) - 1));                  \
            int k1 = k0 | (1 << b);                                                 \
            float2 a0 = amp[k0], a1 = amp[k1];                                      \
            float2 s0 = swp(a0), s1 = swp(a1);                                      \
            amp[k0] = fma2(cd,  a0, fma2(cds0, s0, fma2(co0, a1, mul2(cos_, s1)))); \
            amp[k1] = fma2(co1, a0, fma2(cos_, s0, fma2(cd,  a1, mul2(cds1, s1)))); \
        }                                                                           \
    }

    #pragma unroll 1
    for (int l = 0; l < DEPTH; l++) {
        const int gb = l * NQ;
        float2* bufA = sv;            // trips alternate buffers: A, B, A
        float2* bufB = sv + DIM;

        // -- layout A reg gates: local bits 0..3 = qubits 11..8 --
        #pragma unroll
        for (int b = 0; b < 4; b++)
            GATE_REG(gb + 11 - b)

        // -- trip 1: A -> B  (B: k'=i[7:4], lane'=(i[8]<<4)|i[3:0], w'=w) --
        #pragma unroll
        for (int k = 0; k < 16; k++)
            bufA[swz((w << 9) | (lane << 4) | k)] = amp[k];
        __syncthreads();
        #pragma unroll
        for (int k = 0; k < 16; k++)
            amp[k] = bufA[swz((w << 9) | (l4 << 8) | (k << 4) | llo)];

        // -- layout B reg gates: local bits 4..7 = qubits 7..4 --
        #pragma unroll
        for (int b = 0; b < 4; b++)
            GATE_REG(gb + 7 - b)

        // -- trip 2: B -> C  (C: k'=i[11:8], lane'=i[7:3], w'=i[2:0]) --
        #pragma unroll
        for (int k = 0; k < 16; k++)
            bufB[swz((w << 9) | (l4 << 8) | (k << 4) | llo)] = amp[k];
        __syncthreads();
        #pragma unroll
        for (int k = 0; k < 16; k++)
            amp[k] = bufB[swz((k << 8) | (lane << 3) | w)];

        // -- layout C reg gates: local bits 8..11 = qubits 3..0 --
        #pragma unroll
        for (int b = 0; b < 4; b++)
            GATE_REG(gb + 3 - b)

        // -- trip 3: CNOT-ring scatter, back to layout A --
        #pragma unroll
        for (int k = 0; k < 16; k++) {
            int x  = (k << 8) | (lane << 3) | w;
            int ys = x;
            ys ^= ys >> 1; ys ^= ys >> 2; ys ^= ys >> 4; ys ^= ys >> 8;
            int y = (ys & 0x7FF) | (((ys ^ (x >> 11)) & 1) << 11);
            bufA[swz(y)] = amp[k];
        }
        __syncthreads();
        #pragma unroll
        for (int k = 0; k < 16; k++)
            amp[k] = bufA[swz((w << 9) | (lane << 4) | k)];
        __syncthreads();   // protects bufA reuse at next layer's trip 1
    }

    // ---- measurement from registers (layout A) ----
    float P = 0.0f;
    float zb[4] = {0.0f, 0.0f, 0.0f, 0.0f};
    #pragma unroll
    for (int k = 0; k < 16; k++) {
        float pk = amp[k].x*amp[k].x + amp[k].y*amp[k].y;
        P += pk;
        #pragma unroll
        for (int b = 0; b < 4; b++)
            zb[b] += ((k >> b) & 1) ? -pk : pk;
    }
    float z[NQ];
    const int hi = (w << 9) | (lane << 4);
    #pragma unroll
    for (int q = 0; q < 8; q++)
        z[q] = ((hi >> (11 - q)) & 1) ? -P : P;
    #pragma unroll
    for (int q = 8; q < 12; q++)
        z[q] = zb[11 - q];

    #pragma unroll
    for (int q = 0; q < NQ; q++) {
        #pragma unroll
        for (int s = 16; s > 0; s >>= 1)
            z[q] += __shfl_xor_sync(0xffffffffu, z[q], s);
    }
    if (lane == 0) {
        #pragma unroll
        for (int q = 0; q < NQ; q++) sh_red[w*NQ + q] = z[q];
    }
    __syncthreads();
    if (tid < NQ) {
        float acc = 0.0f;
        #pragma unroll
        for (int ww = 0; ww < TPB/32; ww++) acc += sh_red[ww*NQ + tid];
        sh_meas[tid] = acc;
    }
    __syncthreads();

    // ---- back MLP ----
    if (tid < HID) {
        float acc = b3[tid];
        #pragma unroll
        for (int k = 0; k < NQ; k++)
            acc += sh_meas[k] * W3[k*HID + tid];
        sh_h2[tid] = tanhf(acc);
    }
    __syncthreads();
    if (tid < 2) {
        float acc = b4[tid];
        #pragma unroll
        for (int j = 0; j < HID; j++)
            acc += sh_h2[j] * W4[j*2 + tid];
        out[row*2 + tid] = acc;
    }
}

extern "C" void kernel_launch(void* const* d_in, const int* in_sizes, int n_in,
                              void* d_out, int out_size)
{
    const float* noise = (const float*)d_in[0];
    const float* W1 = (const float*)d_in[1];
    const float* b1 = (const float*)d_in[2];
    const float* W2 = (const float*)d_in[3];
    const float* b2 = (const float*)d_in[4];
    const float* W3 = (const float*)d_in[5];
    const float* b3 = (const float*)d_in[6];
    const float* W4 = (const float*)d_in[7];
    const float* b4 = (const float*)d_in[8];
    float* out = (float*)d_out;

    static int configured = 0;
    if (!configured) {
        cudaFuncSetAttribute(qgen_kernel,
                             cudaFuncAttributeMaxDynamicSharedMemorySize,
                             2 * DIM * sizeof(float2));
        configured = 1;
    }

    int batch = in_sizes[0] / NQ;   // 4096
    qgen_kernel<<<batch, TPB, 2 * DIM * sizeof(float2)>>>(
        noise, W1, b1, W2, b2, W3, b3, W4, b4, out);
}